// round 2
// baseline (speedup 1.0000x reference)
#include <cuda_runtime.h>
#include <cuda_bf16.h>
#include <math.h>

// Problem constants
#define CIN   256
#define COUT  128
#define KK    9
#define H0    64
#define W0    64
#define HH    128   // upsampled H
#define WW    128   // upsampled W
#define NB    2

// Scratch (device globals — no allocations allowed)
__device__ float g_up[NB * COUT * HH * WW];          // 16 MB: transposed-conv output
__device__ float g_wr[KK * COUT * CIN];              // deform weights: [kk][ci][o]
__device__ float g_wt2[KK * CIN * COUT];             // tconv weights: [ky][kx][ci][co] (pre-flipped)
__device__ int   g_sy[NB][KK];
__device__ int   g_sx[NB][KK];
__device__ float g_cw[NB][KK][4];

// ---------------------------------------------------------------------------
// Kernel 1: reorder weights into lane-contiguous layouts
// ---------------------------------------------------------------------------
__global__ void reorder_kernel(const float* __restrict__ tw) {
    int i = blockIdx.x * blockDim.x + threadIdx.x;
    if (i >= KK * COUT * CIN) return;
    // g_wr[kk][ci][o] = tw[o][ci][kk]
    {
        int o  = i & (CIN - 1);
        int ci = (i >> 8) & (COUT - 1);
        int kk = i >> 15;
        g_wr[i] = tw[(o * COUT + ci) * KK + kk];
    }
    // g_wt2[(ky*3+kx)][ci][co] = tw[ci][co][2-ky][2-kx]
    {
        int co = i & (COUT - 1);
        int ci = (i >> 7) & (CIN - 1);
        int k2 = i >> 15;
        int ky = k2 / 3, kx = k2 % 3;
        g_wt2[i] = tw[(ci * COUT + co) * KK + (2 - ky) * 3 + (2 - kx)];
    }
}

// ---------------------------------------------------------------------------
// Kernel 2: offset branch (center-tap only, spatially constant) + bilinear
//           decomposition into integer shifts + 4 corner weights.
// ---------------------------------------------------------------------------
__global__ void offsets_kernel(const float* __restrict__ lat,
                               const float* __restrict__ w1,
                               const float* __restrict__ b1,
                               const float* __restrict__ w2,
                               const float* __restrict__ b2) {
    __shared__ float h[NB][64];
    __shared__ float oc[NB][18];
    int tid = threadIdx.x;
    if (tid < NB * 64) {
        int n = tid >> 6, j = tid & 63;
        float s = b1[j];
        #pragma unroll 4
        for (int i = 0; i < COUT; i++)
            s += lat[n * COUT + i] * w1[(j * COUT + i) * KK + 4];
        h[n][j] = fmaxf(s, 0.f);
    }
    __syncthreads();
    if (tid < NB * 18) {
        int n = tid / 18, c = tid % 18;
        float s = b2[c];
        #pragma unroll 4
        for (int j = 0; j < 64; j++)
            s += h[n][j] * w2[(c * 64 + j) * KK + 4];
        oc[n][c] = tanhf(s);
    }
    __syncthreads();
    if (tid < NB * KK) {
        int n = tid / KK, kk = tid % KK;
        float oy = oc[n][2 * kk], ox = oc[n][2 * kk + 1];
        float fy = floorf(oy), fx = floorf(ox);
        float dy = oy - fy,  dx = ox - fx;
        g_sy[n][kk] = (kk / 3 - 1) + (int)fy;
        g_sx[n][kk] = (kk % 3 - 1) + (int)fx;
        g_cw[n][kk][0] = (1.f - dy) * (1.f - dx);
        g_cw[n][kk][1] = (1.f - dy) * dx;
        g_cw[n][kk][2] = dy * (1.f - dx);
        g_cw[n][kk][3] = dy * dx;
    }
}

// ---------------------------------------------------------------------------
// Kernel 3: transposed conv (stride 2, pad 1, out_pad 1) exploiting parity.
// Block: 128 threads (one per co). Tile: 8 consecutive X at fixed (n, Y).
// up[n,co,Y,X] = sum_{ky,ci} wt2[ky][kx][ci][co] * x[n,ci,(Y+ky-1)/2,(X+kx-1)/2]
// ---------------------------------------------------------------------------
__global__ void tconv_kernel(const float* __restrict__ x,
                             const float* __restrict__ wt2) {
    const int n  = blockIdx.z;
    const int Y  = blockIdx.y;
    const int X0 = blockIdx.x * 8;     // even
    const int co = threadIdx.x;
    const int b  = X0 >> 1;

    float acc[8];
    #pragma unroll
    for (int p = 0; p < 8; p++) acc[p] = 0.f;

    for (int ky = 0; ky < 3; ky++) {
        int t = Y + ky - 1;
        if (t & 1) continue;          // parity (also filters t = -1)
        int y0 = t >> 1;
        if (y0 >= H0) continue;
        const float* wky = wt2 + ky * 3 * CIN * COUT;
        #pragma unroll 2
        for (int ci = 0; ci < CIN; ci++) {
            const float* xp = x + ((n * CIN + ci) * H0 + y0) * W0 + b;
            float xr[5];
            #pragma unroll
            for (int j = 0; j < 5; j++)
                xr[j] = (b + j < W0) ? xp[j] : 0.f;
            float w0 = wky[(0 * CIN + ci) * COUT + co];
            float w1 = wky[(1 * CIN + ci) * COUT + co];
            float w2 = wky[(2 * CIN + ci) * COUT + co];
            // even pixels (kx=1)
            acc[0] += w1 * xr[0]; acc[2] += w1 * xr[1];
            acc[4] += w1 * xr[2]; acc[6] += w1 * xr[3];
            // odd pixels (kx=0 and kx=2)
            acc[1] += w0 * xr[0] + w2 * xr[1];
            acc[3] += w0 * xr[1] + w2 * xr[2];
            acc[5] += w0 * xr[2] + w2 * xr[3];
            acc[7] += w0 * xr[3] + w2 * xr[4];
        }
    }
    float* up = g_up + ((n * COUT + co) * HH + Y) * WW + X0;
    #pragma unroll
    for (int p = 0; p < 8; p++) up[p] = acc[p];
}

// ---------------------------------------------------------------------------
// Kernel 4: deformable conv with spatially-constant offsets.
// out[n,o,y,x] = sum_kk sum_ci Wr[kk][ci][o] * s_kk[ci][x]
//   s_kk[ci][x] = sum of 4 corner-weighted shifted reads of g_up (zero-pad).
// Block: 256 thr. Tile: 16 pixels (x) at fixed (n,y). Each thread: 16 o's.
// ---------------------------------------------------------------------------
__global__ void __launch_bounds__(256, 2)
deform_kernel(const float* __restrict__ wr, float* __restrict__ out) {
    const int n   = blockIdx.z;
    const int y   = blockIdx.y;
    const int x0  = blockIdx.x * 16;
    const int tid = threadIdx.x;
    const int pix = tid & 15;
    const int og  = tid >> 4;          // 0..15, each handles 16 o's

    __shared__ float s[COUT * 16];     // 8 KB
    __shared__ int   ssy[KK], ssx[KK];
    __shared__ float scw[KK][4];
    if (tid < KK) { ssy[tid] = g_sy[n][tid]; ssx[tid] = g_sx[n][tid]; }
    if (tid < KK * 4) scw[tid >> 2][tid & 3] = g_cw[n][tid >> 2][tid & 3];
    __syncthreads();

    float acc[16];
    #pragma unroll
    for (int i = 0; i < 16; i++) acc[i] = 0.f;

    const float* upn = g_up + n * COUT * HH * WW;

    for (int kk = 0; kk < KK; kk++) {
        const int  sy  = ssy[kk], sx = ssx[kk];
        const float c00 = scw[kk][0], c01 = scw[kk][1];
        const float c10 = scw[kk][2], c11 = scw[kk][3];
        const int  yy0 = y + sy;
        const bool yin0 = (unsigned)yy0 < HH;
        const bool yin1 = (unsigned)(yy0 + 1) < HH;

        // fill sampled tile: 128 ci x 16 pix, 8 elems per thread, coalesced in x
        #pragma unroll
        for (int r = 0; r < 8; r++) {
            int idx = tid + r * 256;
            int ci = idx >> 4, p = idx & 15;
            int xx0 = x0 + p + sx;
            bool xin0 = (unsigned)xx0 < WW;
            bool xin1 = (unsigned)(xx0 + 1) < WW;
            const float* upc = upn + ci * HH * WW;
            float v = 0.f;
            if (yin0) {
                const float* row = upc + yy0 * WW;
                if (xin0) v += c00 * row[xx0];
                if (xin1) v += c01 * row[xx0 + 1];
            }
            if (yin1) {
                const float* row = upc + (yy0 + 1) * WW;
                if (xin0) v += c10 * row[xx0];
                if (xin1) v += c11 * row[xx0 + 1];
            }
            s[ci * 16 + p] = v;
        }
        __syncthreads();

        // register-blocked contraction: acc[0..15] over 16 o's
        const float* wk = wr + kk * COUT * CIN + og * 16;
        #pragma unroll 2
        for (int ci = 0; ci < COUT; ci++) {
            float sv = s[ci * 16 + pix];
            const float4* w4 = (const float4*)(wk + ci * CIN);
            float4 a = w4[0], bb = w4[1], c = w4[2], d = w4[3];
            acc[0]  += a.x  * sv; acc[1]  += a.y  * sv;
            acc[2]  += a.z  * sv; acc[3]  += a.w  * sv;
            acc[4]  += bb.x * sv; acc[5]  += bb.y * sv;
            acc[6]  += bb.z * sv; acc[7]  += bb.w * sv;
            acc[8]  += c.x  * sv; acc[9]  += c.y  * sv;
            acc[10] += c.z  * sv; acc[11] += c.w  * sv;
            acc[12] += d.x  * sv; acc[13] += d.y  * sv;
            acc[14] += d.z  * sv; acc[15] += d.w  * sv;
        }
        __syncthreads();
    }

    float* op = out + ((n * CIN + og * 16) * HH + y) * WW + x0 + pix;
    #pragma unroll
    for (int i = 0; i < 16; i++) op[i * HH * WW] = acc[i];
}

// ---------------------------------------------------------------------------
extern "C" void kernel_launch(void* const* d_in, const int* in_sizes, int n_in,
                              void* d_out, int out_size) {
    const float* x   = (const float*)d_in[0];   // [2,256,64,64]
    const float* lat = (const float*)d_in[1];   // [2,128,1,1]
    const float* tw  = (const float*)d_in[2];   // [256,128,3,3]
    const float* w1  = (const float*)d_in[3];   // [64,128,3,3]
    const float* b1  = (const float*)d_in[4];   // [64]
    const float* w2  = (const float*)d_in[5];   // [18,64,3,3]
    const float* b2  = (const float*)d_in[6];   // [18]
    float* out = (float*)d_out;                 // [2,256,128,128]

    float* wr_ptr;
    float* wt2_ptr;
    cudaGetSymbolAddress((void**)&wr_ptr, g_wr);
    cudaGetSymbolAddress((void**)&wt2_ptr, g_wt2);

    reorder_kernel<<<(KK * COUT * CIN + 255) / 256, 256>>>(tw);
    offsets_kernel<<<1, 128>>>(lat, w1, b1, w2, b2);
    {
        dim3 grid(WW / 8, HH, NB);
        tconv_kernel<<<grid, COUT>>>(x, wt2_ptr);
    }
    {
        dim3 grid(WW / 16, HH, NB);
        deform_kernel<<<grid, 256>>>(wr_ptr, out);
    }
}

// round 3
// speedup vs baseline: 1.6343x; 1.6343x over previous
#include <cuda_runtime.h>
#include <cuda_bf16.h>
#include <math.h>

// Problem constants
#define CIN   256
#define COUT  128
#define KK    9
#define H0    64
#define W0    64
#define HH    128   // upsampled H
#define WW    128   // upsampled W
#define NB    2

#define CI_CHUNK 32

// Scratch (device globals — no allocations allowed)
__device__ float g_up[NB * COUT * HH * WW];          // 16 MB: transposed-conv output
__device__ float g_wr[KK * COUT * CIN];              // deform weights: [kk][ci][o]
__device__ float g_wt2[KK * CIN * COUT];             // tconv weights: [ky][kx][ci][co] (pre-flipped)
__device__ int   g_sy[NB][KK];
__device__ int   g_sx[NB][KK];
__device__ float g_cw[NB][KK][4];

// ---------------------------------------------------------------------------
// Kernel 1: reorder weights into lane-contiguous layouts
// ---------------------------------------------------------------------------
__global__ void reorder_kernel(const float* __restrict__ tw) {
    int i = blockIdx.x * blockDim.x + threadIdx.x;
    if (i >= KK * COUT * CIN) return;
    // g_wr[kk][ci][o] = tw[o][ci][kk]
    {
        int o  = i & (CIN - 1);
        int ci = (i >> 8) & (COUT - 1);
        int kk = i >> 15;
        g_wr[i] = tw[(o * COUT + ci) * KK + kk];
    }
    // g_wt2[(ky*3+kx)][ci][co] = tw[ci][co][2-ky][2-kx]
    {
        int co = i & (COUT - 1);
        int ci = (i >> 7) & (CIN - 1);
        int k2 = i >> 15;
        int ky = k2 / 3, kx = k2 % 3;
        g_wt2[i] = tw[(ci * COUT + co) * KK + (2 - ky) * 3 + (2 - kx)];
    }
}

// ---------------------------------------------------------------------------
// Kernel 2: offset branch (center-tap only, spatially constant) + bilinear
//           decomposition into integer shifts + 4 corner weights.
// ---------------------------------------------------------------------------
__global__ void offsets_kernel(const float* __restrict__ lat,
                               const float* __restrict__ w1,
                               const float* __restrict__ b1,
                               const float* __restrict__ w2,
                               const float* __restrict__ b2) {
    __shared__ float h[NB][64];
    __shared__ float oc[NB][18];
    int tid = threadIdx.x;
    if (tid < NB * 64) {
        int n = tid >> 6, j = tid & 63;
        float s = b1[j];
        #pragma unroll 4
        for (int i = 0; i < COUT; i++)
            s += lat[n * COUT + i] * w1[(j * COUT + i) * KK + 4];
        h[n][j] = fmaxf(s, 0.f);
    }
    __syncthreads();
    if (tid < NB * 18) {
        int n = tid / 18, c = tid % 18;
        float s = b2[c];
        #pragma unroll 4
        for (int j = 0; j < 64; j++)
            s += h[n][j] * w2[(c * 64 + j) * KK + 4];
        oc[n][c] = tanhf(s);
    }
    __syncthreads();
    if (tid < NB * KK) {
        int n = tid / KK, kk = tid % KK;
        float oy = oc[n][2 * kk], ox = oc[n][2 * kk + 1];
        float fy = floorf(oy), fx = floorf(ox);
        float dy = oy - fy,  dx = ox - fx;
        g_sy[n][kk] = (kk / 3 - 1) + (int)fy;
        g_sx[n][kk] = (kk % 3 - 1) + (int)fx;
        g_cw[n][kk][0] = (1.f - dy) * (1.f - dx);
        g_cw[n][kk][1] = (1.f - dy) * dx;
        g_cw[n][kk][2] = dy * (1.f - dx);
        g_cw[n][kk][3] = dy * dx;
    }
}

// ---------------------------------------------------------------------------
// Kernel 3: transposed conv as parity-split GEMM.
// Block: (Y, x-parity sX, n). Output tile: 128 co x 64 px (X = 2*j + sX).
// Valid taps: Y even -> ky=1; Y odd -> ky in {0,2}. sX=0 -> kx=1; sX=1 -> kx in {0,2}.
// Each thread computes an 8co x 4px micro-tile.
// ---------------------------------------------------------------------------
__global__ void __launch_bounds__(256)
tconv_kernel(const float* __restrict__ x, const float* __restrict__ wt2) {
    const int Y   = blockIdx.x;
    const int sX  = blockIdx.y;
    const int n   = blockIdx.z;
    const int tid = threadIdx.x;

    __shared__ __align__(16) float wA[16][128];
    __shared__ __align__(16) float xs[16][64];

    const int og = tid >> 4;     // 0..15: co group of 8
    const int pg = tid & 15;     // 0..15: px group of 4

    float acc[8][4];
    #pragma unroll
    for (int i = 0; i < 8; i++)
        #pragma unroll
        for (int j = 0; j < 4; j++) acc[i][j] = 0.f;

    int kylist[2]; int nky = 0;
    if (Y & 1) {
        kylist[nky++] = 0;                 // y0 = (Y-1)/2
        if (Y + 1 < HH) kylist[nky++] = 2; // y0 = (Y+1)/2 (skip at Y=127)
    } else {
        kylist[nky++] = 1;                 // y0 = Y/2
    }
    int kxlist[2]; int nkx = 0;
    if (sX == 0) { kxlist[nkx++] = 1; }
    else         { kxlist[nkx++] = 0; kxlist[nkx++] = 2; }

    const int co_f = tid & 127, rr_f = tid >> 7;   // wA fill mapping
    const int j_f  = tid & 63,  cr_f = tid >> 6;   // xs fill mapping

    for (int a_ = 0; a_ < nky; a_++) {
        const int ky = kylist[a_];
        const int y0 = (Y + ky - 1) >> 1;
        const float* xbase = x + (n * CIN * H0 + y0) * W0;
        for (int b_ = 0; b_ < nkx; b_++) {
            const int kx = kxlist[b_];
            const int d  = (sX + kx - 1) >> 1;     // 0 or 1
            const float* wtap = wt2 + (ky * 3 + kx) * CIN * COUT;
            const int src = j_f + d;
            const bool sok = src < W0;

            for (int c0 = 0; c0 < CIN; c0 += 16) {
                #pragma unroll
                for (int r = 0; r < 8; r++)
                    wA[rr_f + 2 * r][co_f] = wtap[(c0 + rr_f + 2 * r) * COUT + co_f];
                #pragma unroll
                for (int r = 0; r < 4; r++) {
                    int ci = cr_f + 4 * r;
                    xs[ci][j_f] = sok ? xbase[(c0 + ci) * H0 * W0 + src] : 0.f;
                }
                __syncthreads();

                #pragma unroll 4
                for (int ci = 0; ci < 16; ci++) {
                    float4 a0 = *(const float4*)&wA[ci][og * 8];
                    float4 a1 = *(const float4*)&wA[ci][og * 8 + 4];
                    float4 b0 = *(const float4*)&xs[ci][pg * 4];
                    float av[8] = {a0.x, a0.y, a0.z, a0.w, a1.x, a1.y, a1.z, a1.w};
                    float bv[4] = {b0.x, b0.y, b0.z, b0.w};
                    #pragma unroll
                    for (int i = 0; i < 8; i++)
                        #pragma unroll
                        for (int j = 0; j < 4; j++)
                            acc[i][j] += av[i] * bv[j];
                }
                __syncthreads();
            }
        }
    }

    #pragma unroll
    for (int i = 0; i < 8; i++) {
        float* up = g_up + ((n * COUT + og * 8 + i) * HH + Y) * WW + sX;
        #pragma unroll
        for (int j = 0; j < 4; j++)
            up[2 * (pg * 4 + j)] = acc[i][j];
    }
}

// ---------------------------------------------------------------------------
// Kernel 4: deformable conv as GEMM with on-the-fly sampled S tiles.
// Block: (y, o-tile of 128, n). Output tile: 128 o x 128 px (full row).
// K = 9 taps x 256 ci, chunked by CI_CHUNK. Thread: 8o x 8px micro-tile.
// ---------------------------------------------------------------------------
__global__ void __launch_bounds__(256, 2)
deform_kernel(const float* __restrict__ wr, float* __restrict__ out) {
    const int y   = blockIdx.x;
    const int ob  = blockIdx.y;   // 0,1: which 128 of the 256 outputs
    const int n   = blockIdx.z;
    const int tid = threadIdx.x;

    __shared__ __align__(16) float wA[CI_CHUNK][128];
    __shared__ __align__(16) float s[CI_CHUNK][128];
    __shared__ int   ssy[KK], ssx[KK];
    __shared__ float scw[KK][4];
    if (tid < KK) { ssy[tid] = g_sy[n][tid]; ssx[tid] = g_sx[n][tid]; }
    if (tid < KK * 4) ((float*)scw)[tid] = ((const float*)g_cw[n])[tid];
    __syncthreads();

    const int og = tid >> 4;      // 0..15: o group of 8
    const int pg = tid & 15;      // 0..15: px group of 8
    const int px = tid & 127;     // fill mapping
    const int cr = tid >> 7;      // 0/1

    float acc[8][8];
    #pragma unroll
    for (int i = 0; i < 8; i++)
        #pragma unroll
        for (int j = 0; j < 8; j++) acc[i][j] = 0.f;

    const float* upn = g_up + n * COUT * HH * WW;

    for (int kk = 0; kk < KK; kk++) {
        const int   sy  = ssy[kk], sx = ssx[kk];
        const float c00 = scw[kk][0], c01 = scw[kk][1];
        const float c10 = scw[kk][2], c11 = scw[kk][3];
        const int   yy0 = y + sy;
        const bool  yin0 = (unsigned)yy0 < HH;
        const bool  yin1 = (unsigned)(yy0 + 1) < HH;
        const int   xx   = px + sx;
        const bool  xin0 = (unsigned)xx < WW;
        const bool  xin1 = (unsigned)(xx + 1) < WW;
        const float* wkk = wr + kk * COUT * CIN + ob * 128;

        for (int c0 = 0; c0 < COUT; c0 += CI_CHUNK) {
            // fill weight tile: wA[ci][o_local]
            #pragma unroll
            for (int r = 0; r < CI_CHUNK / 2; r++) {
                int ci = cr + 2 * r;
                wA[ci][px] = wkk[(c0 + ci) * CIN + px];
            }
            // fill sampled tile: s[ci][px]
            #pragma unroll
            for (int r = 0; r < CI_CHUNK / 2; r++) {
                int ci = cr + 2 * r;
                const float* upc = upn + (c0 + ci) * HH * WW;
                float v = 0.f;
                if (yin0) {
                    const float* row = upc + yy0 * WW;
                    if (xin0) v += c00 * row[xx];
                    if (xin1) v += c01 * row[xx + 1];
                }
                if (yin1) {
                    const float* row = upc + (yy0 + 1) * WW;
                    if (xin0) v += c10 * row[xx];
                    if (xin1) v += c11 * row[xx + 1];
                }
                s[ci][px] = v;
            }
            __syncthreads();

            #pragma unroll 4
            for (int ci = 0; ci < CI_CHUNK; ci++) {
                float4 a0 = *(const float4*)&wA[ci][og * 8];
                float4 a1 = *(const float4*)&wA[ci][og * 8 + 4];
                float4 b0 = *(const float4*)&s[ci][pg * 8];
                float4 b1 = *(const float4*)&s[ci][pg * 8 + 4];
                float av[8] = {a0.x, a0.y, a0.z, a0.w, a1.x, a1.y, a1.z, a1.w};
                float bv[8] = {b0.x, b0.y, b0.z, b0.w, b1.x, b1.y, b1.z, b1.w};
                #pragma unroll
                for (int i = 0; i < 8; i++)
                    #pragma unroll
                    for (int j = 0; j < 8; j++)
                        acc[i][j] += av[i] * bv[j];
            }
            __syncthreads();
        }
    }

    #pragma unroll
    for (int i = 0; i < 8; i++) {
        float* op = out + ((n * CIN + ob * 128 + og * 8 + i) * HH + y) * WW + pg * 8;
        *(float4*)op       = make_float4(acc[i][0], acc[i][1], acc[i][2], acc[i][3]);
        *(float4*)(op + 4) = make_float4(acc[i][4], acc[i][5], acc[i][6], acc[i][7]);
    }
}

// ---------------------------------------------------------------------------
extern "C" void kernel_launch(void* const* d_in, const int* in_sizes, int n_in,
                              void* d_out, int out_size) {
    const float* x   = (const float*)d_in[0];   // [2,256,64,64]
    const float* lat = (const float*)d_in[1];   // [2,128,1,1]
    const float* tw  = (const float*)d_in[2];   // [256,128,3,3]
    const float* w1  = (const float*)d_in[3];   // [64,128,3,3]
    const float* b1  = (const float*)d_in[4];   // [64]
    const float* w2  = (const float*)d_in[5];   // [18,64,3,3]
    const float* b2  = (const float*)d_in[6];   // [18]
    float* out = (float*)d_out;                 // [2,256,128,128]

    float* wr_ptr;
    float* wt2_ptr;
    cudaGetSymbolAddress((void**)&wr_ptr, g_wr);
    cudaGetSymbolAddress((void**)&wt2_ptr, g_wt2);

    reorder_kernel<<<(KK * COUT * CIN + 255) / 256, 256>>>(tw);
    offsets_kernel<<<1, 128>>>(lat, w1, b1, w2, b2);
    {
        dim3 grid(HH, 2, NB);   // (Y, x-parity, n)
        tconv_kernel<<<grid, 256>>>(x, wt2_ptr);
    }
    {
        dim3 grid(HH, 2, NB);   // (y, o-tile, n)
        deform_kernel<<<grid, 256>>>(wr_ptr, out);
    }
}